// round 8
// baseline (speedup 1.0000x reference)
#include <cuda_runtime.h>
#include <cuda_fp16.h>
#include <cstdint>

#define NTOK   8192
#define EDIM   2048
#define NEXP   8
#define CAPACITY 2560
#define ROWS_MAX 4096
#define KC     64
#define NKC    (EDIM/KC)     // 32 K-chunks
#define MTILE  256
#define RB_CNT (ROWS_MAX/MTILE)   // 16

// ---------------- device scratch (no allocs allowed) ----------------
__device__ int    g_count[NEXP];
__device__ float  g_probSum[NEXP];
__device__ int    g_tok[NEXP*NTOK];
__device__ float  g_wgt[NEXP*NTOK];
__device__ int    g_pos[NEXP*NTOK];
__device__ int    g_code[NTOK*2];
__device__ unsigned char g_drop[NEXP*NTOK];
__device__ __half g_w16[(size_t)2*NEXP*EDIM*EDIM];        // 134 MB (w1|w2 fp16)
__device__ __half g_x16[(size_t)NTOK*EDIM];               // 33 MB
__device__ __half g_h16[(size_t)NEXP*ROWS_MAX*EDIM];      // 134 MB
__device__ float  g_ybuf[(size_t)NEXP*ROWS_MAX*EDIM];     // 268 MB

// ---------------- helpers ----------------
__device__ __forceinline__ uint32_t smem_u32(const void* p){
  uint32_t a; asm("{ .reg .u64 t; cvta.to.shared.u64 t, %1; cvt.u32.u64 %0, t; }" : "=r"(a) : "l"(p));
  return a;
}
__device__ __forceinline__ void cpa16(uint32_t dst, const void* src){
  asm volatile("cp.async.cg.shared.global [%0], [%1], 16;" :: "r"(dst), "l"(src));
}

// ---------------- fp32 -> fp16 conversion of weights and x (+ counter init) ----------------
__global__ void convert_kernel(const float* __restrict__ w1, const float* __restrict__ w2,
                               const float* __restrict__ x){
  if (blockIdx.x == 0 && threadIdx.x < NEXP){
    g_count[threadIdx.x] = 0; g_probSum[threadIdx.x] = 0.f;
  }
  const size_t NW = (size_t)NEXP*EDIM*EDIM;
  const size_t NX = (size_t)NTOK*EDIM;
  size_t i = (size_t)blockIdx.x*blockDim.x + threadIdx.x;
  size_t stride = (size_t)gridDim.x*blockDim.x;
  uint2* o1 = reinterpret_cast<uint2*>(g_w16);
  uint2* o2 = reinterpret_cast<uint2*>(g_w16 + NW);
  uint2* ox = reinterpret_cast<uint2*>(g_x16);
  const float4* s1 = reinterpret_cast<const float4*>(w1);
  const float4* s2 = reinterpret_cast<const float4*>(w2);
  const float4* sx = reinterpret_cast<const float4*>(x);
  for (size_t j=i; j<NW/4; j+=stride){
    float4 v = s1[j];
    __half2 a = __floats2half2_rn(v.x,v.y), b = __floats2half2_rn(v.z,v.w);
    o1[j] = make_uint2(*(uint32_t*)&a, *(uint32_t*)&b);
    v = s2[j];
    a = __floats2half2_rn(v.x,v.y); b = __floats2half2_rn(v.z,v.w);
    o2[j] = make_uint2(*(uint32_t*)&a, *(uint32_t*)&b);
  }
  for (size_t j=i; j<NX/4; j+=stride){
    float4 v = sx[j];
    __half2 a = __floats2half2_rn(v.x,v.y), b = __floats2half2_rn(v.z,v.w);
    ox[j] = make_uint2(*(uint32_t*)&a, *(uint32_t*)&b);
  }
}

// ---------------- router: warp per token ----------------
__global__ void router_kernel(const float* __restrict__ x, const float* __restrict__ gw,
                              const float* __restrict__ gb, const float* __restrict__ temp){
  int t = (int)((blockIdx.x*blockDim.x + threadIdx.x) >> 5);
  int lane = threadIdx.x & 31;
  if (t >= NTOK) return;
  const float* xr = x + (size_t)t * EDIM;
  float acc[8] = {0,0,0,0,0,0,0,0};
  for (int d = lane; d < EDIM; d += 32){
    float xv = xr[d];
    const float4* g4 = reinterpret_cast<const float4*>(gw + (size_t)d*NEXP);
    float4 ga = g4[0], gbv = g4[1];
    acc[0] += xv*ga.x;  acc[1] += xv*ga.y;  acc[2] += xv*ga.z;  acc[3] += xv*ga.w;
    acc[4] += xv*gbv.x; acc[5] += xv*gbv.y; acc[6] += xv*gbv.z; acc[7] += xv*gbv.w;
  }
  #pragma unroll
  for (int off=16; off; off>>=1)
    #pragma unroll
    for (int e=0;e<8;e++) acc[e] += __shfl_down_sync(0xffffffffu, acc[e], off);
  if (lane==0){
    float it = 1.0f / fabsf(temp[0]);
    float p[8]; float m = -1e30f;
    #pragma unroll
    for (int e=0;e<8;e++){ p[e] = (acc[e]+gb[e])*it; m = fmaxf(m, p[e]); }
    float s = 0.f;
    #pragma unroll
    for (int e=0;e<8;e++){ p[e] = expf(p[e]-m); s += p[e]; }
    float inv = 1.f/s;
    #pragma unroll
    for (int e=0;e<8;e++){ p[e] *= inv; atomicAdd(&g_probSum[e], p[e]); }
    int e0 = 0;
    #pragma unroll
    for (int e=1;e<8;e++) if (p[e] > p[e0]) e0 = e;
    int e1 = (e0==0) ? 1 : 0;
    #pragma unroll
    for (int e=0;e<8;e++) if (e!=e0 && p[e] > p[e1]) e1 = e;
    float rs = 1.f/(p[e0]+p[e1]);
    int s0 = atomicAdd(&g_count[e0], 1);
    g_tok[e0*NTOK+s0] = t; g_wgt[e0*NTOK+s0] = p[e0]*rs; g_pos[e0*NTOK+s0] = t*2;
    g_code[t*2+0] = e0*NTOK + s0;
    int s1 = atomicAdd(&g_count[e1], 1);
    g_tok[e1*NTOK+s1] = t; g_wgt[e1*NTOK+s1] = p[e1]*rs; g_pos[e1*NTOK+s1] = t*2+1;
    g_code[t*2+1] = e1*NTOK + s1;
  }
}

// ---------------- capacity filter (exact jax semantics; ~never triggers) ----------------
__global__ void capacity_kernel(){
  int e = blockIdx.x;
  int cnt = g_count[e];
  if (cnt <= CAPACITY) return;
  for (int i = threadIdx.x; i < cnt; i += blockDim.x){
    float wi = g_wgt[e*NTOK+i]; int pi = g_pos[e*NTOK+i];
    int rank = 0;
    for (int j=0;j<cnt;j++){
      float wj = g_wgt[e*NTOK+j];
      if (wj > wi || (wj == wi && g_pos[e*NTOK+j] < pi)) rank++;
    }
    g_drop[e*NTOK+i] = (rank >= CAPACITY) ? 1 : 0;
  }
  __syncthreads();
  for (int i = threadIdx.x; i < cnt; i += blockDim.x)
    if (g_drop[e*NTOK+i]) g_wgt[e*NTOK+i] = 0.f;
}

// ---------------- aux loss ----------------
__global__ void aux_kernel(float* __restrict__ out, int out_size){
  if (threadIdx.x != 0) return;
  float sum = 0.f;
  for (int e=0;e<NEXP;e++) sum += g_probSum[e];
  float mean = sum / NEXP;
  float var = 0.f;
  for (int e=0;e<NEXP;e++){ float d = g_probSum[e]-mean; var += d*d; }
  var /= (NEXP-1);
  float cv = sqrtf(var) / (mean + 1e-10f);
  float bal = 0.f;
  for (int e=0;e<NEXP;e++)
    bal += (g_probSum[e]/(float)NTOK) * ((float)g_count[e]/(float)NTOK);
  bal *= (float)NEXP;
  if (out_size > NTOK*EDIM) out[(size_t)NTOK*EDIM] = bal + 0.01f*cv;
}

// ---------------- fp16 mma.sync GEMM, 256x128x64-chunk, 4-stage, 512 thr ----------------
#define A_ST 32768
#define B_ST 16384
#define STAGE_BYTES (A_ST + B_ST)
#define NSTAGE 4
#define META_OFF (NSTAGE*STAGE_BYTES)       // 196608
#define SMEM_TOTAL (META_OFF + 1280)

template<int MODE>
__device__ __forceinline__ void load_A_half(
    int kt, int slot, int tid, uint32_t sbase,
    const __half* __restrict__ Xg, const int* __restrict__ stok)
{
  int k0 = kt*KC;
  uint32_t ab = sbase + slot*STAGE_BYTES;
  #pragma unroll
  for (int i=0;i<4;i++){
    int idx = tid + i*512;
    int r = idx >> 3, ko = idx & 7;         // r 0..255, k = ko*8
    size_t grow = (MODE==1) ? (size_t)stok[r] : (size_t)r;
    const __half* src = Xg + grow*EDIM + k0 + ko*8;
    // m16xk16 tile (mi=r>>4, ki=ko>>1) packed in 512B
    uint32_t dst = ab + (uint32_t)((((r>>4)*4 + (ko>>1))*512) + ((ko&1)?256:0) + (r&15)*16);
    cpa16(dst, src);
  }
}
__device__ __forceinline__ void load_B_half(
    int kt, int slot, int tid, uint32_t sbase,
    const __half* __restrict__ Wb)
{
  int k0 = kt*KC;
  uint32_t bb = sbase + slot*STAGE_BYTES + A_ST;
  #pragma unroll
  for (int i=0;i<2;i++){
    int idx = tid + i*512;
    int kr = idx >> 4, no = idx & 15;       // kr 0..63, n = no*8
    const __half* src = Wb + (size_t)(k0+kr)*EDIM + no*8;
    // k16xn16 tile (ki=kr>>4, ni=no>>1) packed in 512B
    uint32_t dst = bb + (uint32_t)((((kr>>4)*8 + (no>>1))*512) + ((no&1)?256:0) + (kr&15)*16);
    cpa16(dst, src);
  }
}

template<int MODE>
__global__ void __launch_bounds__(512,1) moe_gemm(
    const float* __restrict__ bias)
{
  int e  = blockIdx.y >> 4;
  int rb = blockIdx.y & 15;
  int cnt = g_count[e]; if (cnt > ROWS_MAX) cnt = ROWS_MAX;
  int row0 = rb * MTILE;
  if (row0 >= cnt) return;
  int rows = cnt - row0; if (rows > MTILE) rows = MTILE;
  int n0 = blockIdx.x * 128;

  extern __shared__ char smem[];
  uint32_t sbase = smem_u32(smem);
  int tid = threadIdx.x, warp = tid>>5, lane = tid&31;
  int* stok = (int*)(smem + META_OFF);

  if (tid < MTILE){
    int tkn = 0;
    if (MODE==1 && tid < rows) tkn = g_tok[e*NTOK + row0 + tid];
    stok[tid] = tkn;
  }
  __syncthreads();

  const __half* Xg = (MODE==1) ? g_x16 : (g_h16 + ((size_t)e*ROWS_MAX + row0)*EDIM);
  const __half* Wb = g_w16 + ((size_t)((MODE-1)*NEXP + e))*EDIM*EDIM + n0;

  float c[4][4][4];
  #pragma unroll
  for (int a=0;a<4;a++)
    #pragma unroll
    for (int b=0;b<4;b++)
      #pragma unroll
      for (int q=0;q<4;q++) c[a][b][q] = 0.f;

  int wm = warp & 3, wn = warp >> 2;   // 4x4 warp grid: 64(M) x 32(N) each

  #pragma unroll
  for (int p=0;p<3;p++){
    load_A_half<MODE>(p, p, tid, sbase, Xg, stok);
    load_B_half(p, p, tid, sbase, Wb);
    asm volatile("cp.async.commit_group;" ::: "memory");
  }

  for (int kt=0; kt<NKC; kt++){
    int slot = kt & 3;
    if      (kt+2 < NKC) asm volatile("cp.async.wait_group 2;" ::: "memory");
    else if (kt+1 < NKC) asm volatile("cp.async.wait_group 1;" ::: "memory");
    else                 asm volatile("cp.async.wait_group 0;" ::: "memory");
    __syncthreads();

    uint32_t ab = sbase + slot*STAGE_BYTES;
    uint32_t bb = ab + A_ST;
    int nslot = (kt+3) & 3;
    bool pref = (kt+3 < NKC);

    #pragma unroll
    for (int ks=0; ks<4; ks++){
      uint32_t a[4][4], b[4][2];
      #pragma unroll
      for (int mf=0; mf<4; mf++){
        uint32_t addr = ab + (uint32_t)(((wm*4+mf)*4 + ks)*512) + lane*16;
        asm volatile("ldmatrix.sync.aligned.m8n8.x4.shared.b16 {%0,%1,%2,%3}, [%4];"
          : "=r"(a[mf][0]),"=r"(a[mf][1]),"=r"(a[mf][2]),"=r"(a[mf][3]) : "r"(addr));
      }
      #pragma unroll
      for (int p=0; p<2; p++){
        uint32_t addr = bb + (uint32_t)((ks*8 + wn*2 + p)*512) + lane*16;
        asm volatile("ldmatrix.sync.aligned.m8n8.x4.trans.shared.b16 {%0,%1,%2,%3}, [%4];"
          : "=r"(b[2*p][0]),"=r"(b[2*p][1]),"=r"(b[2*p+1][0]),"=r"(b[2*p+1][1]) : "r"(addr));
      }
      #pragma unroll
      for (int mf=0; mf<4; mf++)
        #pragma unroll
        for (int nf=0; nf<4; nf++)
          asm volatile("mma.sync.aligned.m16n8k16.row.col.f32.f16.f16.f32 "
            "{%0,%1,%2,%3}, {%4,%5,%6,%7}, {%8,%9}, {%0,%1,%2,%3};"
            : "+f"(c[mf][nf][0]), "+f"(c[mf][nf][1]), "+f"(c[mf][nf][2]), "+f"(c[mf][nf][3])
            : "r"(a[mf][0]),"r"(a[mf][1]),"r"(a[mf][2]),"r"(a[mf][3]),
              "r"(b[nf][0]),"r"(b[nf][1]));

      // interleaved prefetch issue: keep LSU off the chunk-start critical path
      if (ks==0 && pref) load_A_half<MODE>(kt+3, nslot, tid, sbase, Xg, stok);
      if (ks==1 && pref) load_B_half(kt+3, nslot, tid, sbase, Wb);
      if (ks==2 && pref) asm volatile("cp.async.commit_group;" ::: "memory");
    }
  }

  // ---------------- epilogue (registers -> gmem) ----------------
  int lr = lane>>2, lc = lane&3;
  const float* brow = bias + e*EDIM + n0 + wn*32;
  if (MODE==1){
    __half* hb = g_h16 + ((size_t)e*ROWS_MAX + row0)*EDIM + n0 + wn*32;
    #pragma unroll
    for (int nf=0; nf<4; nf++){
      int col = nf*8 + lc*2;
      float bv0 = brow[col], bv1 = brow[col+1];
      #pragma unroll
      for (int mf=0; mf<4; mf++){
        int r_ = wm*64 + mf*16 + lr;
        if (r_ < rows){
          __half2 h = __floats2half2_rn(fmaxf(c[mf][nf][0]+bv0,0.f), fmaxf(c[mf][nf][1]+bv1,0.f));
          *reinterpret_cast<__half2*>(hb + (size_t)r_*EDIM + col) = h;
        }
        if (r_+8 < rows){
          __half2 h = __floats2half2_rn(fmaxf(c[mf][nf][2]+bv0,0.f), fmaxf(c[mf][nf][3]+bv1,0.f));
          *reinterpret_cast<__half2*>(hb + (size_t)(r_+8)*EDIM + col) = h;
        }
      }
    }
  } else {
    float* yb = g_ybuf + ((size_t)e*ROWS_MAX + row0)*EDIM + n0 + wn*32;
    #pragma unroll
    for (int nf=0; nf<4; nf++){
      int col = nf*8 + lc*2;
      float bv0 = brow[col], bv1 = brow[col+1];
      #pragma unroll
      for (int mf=0; mf<4; mf++){
        int r_ = wm*64 + mf*16 + lr;
        if (r_ < rows)
          *reinterpret_cast<float2*>(yb + (size_t)r_*EDIM + col)
              = make_float2(c[mf][nf][0]+bv0, c[mf][nf][1]+bv1);
        if (r_+8 < rows)
          *reinterpret_cast<float2*>(yb + (size_t)(r_+8)*EDIM + col)
              = make_float2(c[mf][nf][2]+bv0, c[mf][nf][3]+bv1);
      }
    }
  }
}

// ---------------- combine: out = x + w0*y0 + w1*y1 ----------------
__global__ void combine_kernel(const float* __restrict__ x, float* __restrict__ out){
  int t = blockIdx.x;
  int c1 = g_code[2*t], c2 = g_code[2*t+1];
  int s1 = c1 & (NTOK-1), s2 = c2 & (NTOK-1);
  float w1v = (s1 < ROWS_MAX) ? g_wgt[c1] : 0.f;
  float w2v = (s2 < ROWS_MAX) ? g_wgt[c2] : 0.f;
  size_t y1o = (s1 < ROWS_MAX) ? ((size_t)(c1>>13)*ROWS_MAX + s1)*EDIM : 0;
  size_t y2o = (s2 < ROWS_MAX) ? ((size_t)(c2>>13)*ROWS_MAX + s2)*EDIM : 0;
  const float4* xr = reinterpret_cast<const float4*>(x + (size_t)t*EDIM);
  const float4* y1 = reinterpret_cast<const float4*>(g_ybuf + y1o);
  const float4* y2 = reinterpret_cast<const float4*>(g_ybuf + y2o);
  float4* o = reinterpret_cast<float4*>(out + (size_t)t*EDIM);
  for (int j = threadIdx.x; j < EDIM/4; j += blockDim.x){
    float4 a = xr[j], b = y1[j], c = y2[j];
    float4 rr;
    rr.x = a.x + w1v*b.x + w2v*c.x;
    rr.y = a.y + w1v*b.y + w2v*c.y;
    rr.z = a.z + w1v*b.z + w2v*c.z;
    rr.w = a.w + w1v*b.w + w2v*c.w;
    o[j] = rr;
  }
}

// ---------------- launch ----------------
extern "C" void kernel_launch(void* const* d_in, const int* in_sizes, int n_in,
                              void* d_out, int out_size){
  const float* x  = (const float*)d_in[0];
  const float* gw = (const float*)d_in[1];
  const float* gb = (const float*)d_in[2];
  const float* tp = (const float*)d_in[3];
  const float* w1 = (const float*)d_in[4];
  const float* b1 = (const float*)d_in[5];
  const float* w2 = (const float*)d_in[6];
  const float* b2 = (const float*)d_in[7];
  float* out = (float*)d_out;

  cudaFuncSetAttribute(moe_gemm<1>, cudaFuncAttributeMaxDynamicSharedMemorySize, SMEM_TOTAL);
  cudaFuncSetAttribute(moe_gemm<2>, cudaFuncAttributeMaxDynamicSharedMemorySize, SMEM_TOTAL);

  convert_kernel<<<1024, 256>>>(w1, w2, x);           // idx 0 (also inits counters)
  router_kernel<<<NTOK/8, 256>>>(x, gw, gb, tp);      // idx 1
  capacity_kernel<<<NEXP, 256>>>();                   // idx 2
  dim3 grid(EDIM/128, NEXP*RB_CNT);
  moe_gemm<1><<<grid, 512, SMEM_TOTAL>>>(b1);         // idx 3  <-- profiled
  moe_gemm<2><<<grid, 512, SMEM_TOTAL>>>(b2);         // idx 4
  aux_kernel<<<1, 32>>>(out, out_size);               // idx 5
  combine_kernel<<<NTOK, 256>>>(x, out);              // idx 6
}

// round 9
// speedup vs baseline: 1.1662x; 1.1662x over previous
#include <cuda_runtime.h>
#include <cuda_fp16.h>
#include <cstdint>

#define NTOK   8192
#define EDIM   2048
#define NEXP   8
#define CAPACITY 2560
#define ROWS_MAX 4096
#define KC     64
#define NKC    (EDIM/KC)     // 32 K-chunks

// ---------------- device scratch (no allocs allowed) ----------------
__device__ int    g_count[NEXP];
__device__ float  g_probSum[NEXP];
__device__ int    g_tok[NEXP*NTOK];
__device__ float  g_wgt[NEXP*NTOK];
__device__ int    g_pos[NEXP*NTOK];
__device__ int    g_code[NTOK*2];
__device__ unsigned char g_drop[NEXP*NTOK];
__device__ __half g_w16[(size_t)2*NEXP*EDIM*EDIM];        // 134 MB (w1|w2 fp16)
__device__ __half g_x16[(size_t)NTOK*EDIM];               // 33 MB
__device__ __half g_h16[(size_t)NEXP*ROWS_MAX*EDIM];      // 134 MB
__device__ float  g_ybuf[(size_t)NEXP*ROWS_MAX*EDIM];     // 268 MB

// ---------------- helpers ----------------
__device__ __forceinline__ uint32_t smem_u32(const void* p){
  uint32_t a; asm("{ .reg .u64 t; cvta.to.shared.u64 t, %1; cvt.u32.u64 %0, t; }" : "=r"(a) : "l"(p));
  return a;
}
__device__ __forceinline__ void cpa16(uint32_t dst, const void* src){
  asm volatile("cp.async.cg.shared.global [%0], [%1], 16;" :: "r"(dst), "l"(src));
}

// ---------------- fp32 -> fp16 conversion of weights and x (+ counter init) ----------------
__global__ void convert_kernel(const float* __restrict__ w1, const float* __restrict__ w2,
                               const float* __restrict__ x){
  if (blockIdx.x == 0 && threadIdx.x < NEXP){
    g_count[threadIdx.x] = 0; g_probSum[threadIdx.x] = 0.f;
  }
  const size_t NW = (size_t)NEXP*EDIM*EDIM;
  const size_t NX = (size_t)NTOK*EDIM;
  size_t i = (size_t)blockIdx.x*blockDim.x + threadIdx.x;
  size_t stride = (size_t)gridDim.x*blockDim.x;
  uint2* o1 = reinterpret_cast<uint2*>(g_w16);
  uint2* o2 = reinterpret_cast<uint2*>(g_w16 + NW);
  uint2* ox = reinterpret_cast<uint2*>(g_x16);
  const float4* s1 = reinterpret_cast<const float4*>(w1);
  const float4* s2 = reinterpret_cast<const float4*>(w2);
  const float4* sx = reinterpret_cast<const float4*>(x);
  for (size_t j=i; j<NW/4; j+=stride){
    float4 v = s1[j];
    __half2 a = __floats2half2_rn(v.x,v.y), b = __floats2half2_rn(v.z,v.w);
    o1[j] = make_uint2(*(uint32_t*)&a, *(uint32_t*)&b);
    v = s2[j];
    a = __floats2half2_rn(v.x,v.y); b = __floats2half2_rn(v.z,v.w);
    o2[j] = make_uint2(*(uint32_t*)&a, *(uint32_t*)&b);
  }
  for (size_t j=i; j<NX/4; j+=stride){
    float4 v = sx[j];
    __half2 a = __floats2half2_rn(v.x,v.y), b = __floats2half2_rn(v.z,v.w);
    ox[j] = make_uint2(*(uint32_t*)&a, *(uint32_t*)&b);
  }
}

// ---------------- router: warp per token ----------------
__global__ void router_kernel(const float* __restrict__ x, const float* __restrict__ gw,
                              const float* __restrict__ gb, const float* __restrict__ temp){
  int t = (int)((blockIdx.x*blockDim.x + threadIdx.x) >> 5);
  int lane = threadIdx.x & 31;
  if (t >= NTOK) return;
  const float* xr = x + (size_t)t * EDIM;
  float acc[8] = {0,0,0,0,0,0,0,0};
  for (int d = lane; d < EDIM; d += 32){
    float xv = xr[d];
    const float4* g4 = reinterpret_cast<const float4*>(gw + (size_t)d*NEXP);
    float4 ga = g4[0], gbv = g4[1];
    acc[0] += xv*ga.x;  acc[1] += xv*ga.y;  acc[2] += xv*ga.z;  acc[3] += xv*ga.w;
    acc[4] += xv*gbv.x; acc[5] += xv*gbv.y; acc[6] += xv*gbv.z; acc[7] += xv*gbv.w;
  }
  #pragma unroll
  for (int off=16; off; off>>=1)
    #pragma unroll
    for (int e=0;e<8;e++) acc[e] += __shfl_down_sync(0xffffffffu, acc[e], off);
  if (lane==0){
    float it = 1.0f / fabsf(temp[0]);
    float p[8]; float m = -1e30f;
    #pragma unroll
    for (int e=0;e<8;e++){ p[e] = (acc[e]+gb[e])*it; m = fmaxf(m, p[e]); }
    float s = 0.f;
    #pragma unroll
    for (int e=0;e<8;e++){ p[e] = expf(p[e]-m); s += p[e]; }
    float inv = 1.f/s;
    #pragma unroll
    for (int e=0;e<8;e++){ p[e] *= inv; atomicAdd(&g_probSum[e], p[e]); }
    int e0 = 0;
    #pragma unroll
    for (int e=1;e<8;e++) if (p[e] > p[e0]) e0 = e;
    int e1 = (e0==0) ? 1 : 0;
    #pragma unroll
    for (int e=0;e<8;e++) if (e!=e0 && p[e] > p[e1]) e1 = e;
    float rs = 1.f/(p[e0]+p[e1]);
    int s0 = atomicAdd(&g_count[e0], 1);
    g_tok[e0*NTOK+s0] = t; g_wgt[e0*NTOK+s0] = p[e0]*rs; g_pos[e0*NTOK+s0] = t*2;
    g_code[t*2+0] = e0*NTOK + s0;
    int s1 = atomicAdd(&g_count[e1], 1);
    g_tok[e1*NTOK+s1] = t; g_wgt[e1*NTOK+s1] = p[e1]*rs; g_pos[e1*NTOK+s1] = t*2+1;
    g_code[t*2+1] = e1*NTOK + s1;
  }
}

// ---------------- capacity filter (exact jax semantics; ~never triggers) ----------------
__global__ void capacity_kernel(){
  int e = blockIdx.x;
  int cnt = g_count[e];
  if (cnt <= CAPACITY) return;
  for (int i = threadIdx.x; i < cnt; i += blockDim.x){
    float wi = g_wgt[e*NTOK+i]; int pi = g_pos[e*NTOK+i];
    int rank = 0;
    for (int j=0;j<cnt;j++){
      float wj = g_wgt[e*NTOK+j];
      if (wj > wi || (wj == wi && g_pos[e*NTOK+j] < pi)) rank++;
    }
    g_drop[e*NTOK+i] = (rank >= CAPACITY) ? 1 : 0;
  }
  __syncthreads();
  for (int i = threadIdx.x; i < cnt; i += blockDim.x)
    if (g_drop[e*NTOK+i]) g_wgt[e*NTOK+i] = 0.f;
}

// ---------------- aux loss ----------------
__global__ void aux_kernel(float* __restrict__ out, int out_size){
  if (threadIdx.x != 0) return;
  float sum = 0.f;
  for (int e=0;e<NEXP;e++) sum += g_probSum[e];
  float mean = sum / NEXP;
  float var = 0.f;
  for (int e=0;e<NEXP;e++){ float d = g_probSum[e]-mean; var += d*d; }
  var /= (NEXP-1);
  float cv = sqrtf(var) / (mean + 1e-10f);
  float bal = 0.f;
  for (int e=0;e<NEXP;e++)
    bal += (g_probSum[e]/(float)NTOK) * ((float)g_count[e]/(float)NTOK);
  bal *= (float)NEXP;
  if (out_size > NTOK*EDIM) out[(size_t)NTOK*EDIM] = bal + 0.01f*cv;
}

// ---------------- fp16 mma.sync GEMM, 128Mx256Nx64K chunks ----------------
// 8 warps (2x4), warp tile 64x64, 1 CTA/SM, XOR-swizzled smem (conflict-free)
// A stage: 128 rows x 128B (16KB): addr = r*128 + ((ko ^ (r&7))<<4), ko=k-octet 0..7
// B stage: 64 k-rows x 512B (32KB): addr = kr*512 + ((no ^ (kr&7))<<4), no=n-octet 0..31
#define A_ST 16384
#define B_ST 32768
#define STAGE_BYTES (A_ST + B_ST)
#define NSTAGE 4
#define META_OFF (NSTAGE*STAGE_BYTES)       // 196608
#define SMEM_TOTAL (META_OFF + 768)

template<int MODE>
__device__ __forceinline__ void load_A(
    int kt, int slot, int tid, uint32_t sbase,
    const __half* __restrict__ Xg, const int* __restrict__ stok)
{
  int k0 = kt*KC;
  uint32_t ab = sbase + slot*STAGE_BYTES;
  #pragma unroll
  for (int i=0;i<4;i++){
    int idx = tid + i*256;
    int r = idx >> 3, ko = idx & 7;
    size_t grow = (MODE==1) ? (size_t)stok[r] : (size_t)r;
    const __half* src = Xg + grow*EDIM + k0 + ko*8;
    uint32_t dst = ab + (uint32_t)(r*128 + ((ko ^ (r&7))<<4));
    cpa16(dst, src);
  }
}
template<int HALF>
__device__ __forceinline__ void load_B(
    int kt, int slot, int tid, uint32_t sbase,
    const __half* __restrict__ Wb)
{
  int k0 = kt*KC;
  uint32_t bb = sbase + slot*STAGE_BYTES + A_ST;
  #pragma unroll
  for (int i=HALF*4;i<HALF*4+4;i++){
    int idx = tid + i*256;
    int kr = idx >> 5, no = idx & 31;
    const __half* src = Wb + (size_t)(k0+kr)*EDIM + no*8;
    uint32_t dst = bb + (uint32_t)(kr*512 + ((no ^ (kr&7))<<4));
    cpa16(dst, src);
  }
}

template<int MODE>
__global__ void __launch_bounds__(256,1) moe_gemm(
    const float* __restrict__ bias)
{
  int e  = blockIdx.y >> 5;
  int rb = blockIdx.y & 31;
  int cnt = g_count[e]; if (cnt > ROWS_MAX) cnt = ROWS_MAX;
  int row0 = rb * 128;
  if (row0 >= cnt) return;
  int rows = cnt - row0; if (rows > 128) rows = 128;
  int n0 = blockIdx.x * 256;

  extern __shared__ char smem[];
  uint32_t sbase = smem_u32(smem);
  int tid = threadIdx.x, warp = tid>>5, lane = tid&31;
  int* stok = (int*)(smem + META_OFF);

  if (tid < 128){
    int tkn = 0;
    if (MODE==1 && tid < rows) tkn = g_tok[e*NTOK + row0 + tid];
    stok[tid] = tkn;
  }
  __syncthreads();

  const __half* Xg = (MODE==1) ? g_x16 : (g_h16 + ((size_t)e*ROWS_MAX + row0)*EDIM);
  const __half* Wb = g_w16 + ((size_t)((MODE-1)*NEXP + e))*EDIM*EDIM + n0;

  float c[4][8][4];
  #pragma unroll
  for (int a=0;a<4;a++)
    #pragma unroll
    for (int b=0;b<8;b++)
      #pragma unroll
      for (int q=0;q<4;q++) c[a][b][q] = 0.f;

  int wm = warp & 1, wn = warp >> 1;   // 2x4 warp grid: 64(M) x 64(N) each

  #pragma unroll
  for (int p=0;p<3;p++){
    load_A<MODE>(p, p, tid, sbase, Xg, stok);
    load_B<0>(p, p, tid, sbase, Wb);
    load_B<1>(p, p, tid, sbase, Wb);
    asm volatile("cp.async.commit_group;" ::: "memory");
  }

  // per-lane fragment coordinates
  int arow_lo = (lane & 15);            // row within 16-row block
  int ako_hi  = (lane >> 4);            // 0/1: which k-octet of the pair
  for (int kt=0; kt<NKC; kt++){
    int slot = kt & 3;
    if      (kt+2 < NKC) asm volatile("cp.async.wait_group 2;" ::: "memory");
    else if (kt+1 < NKC) asm volatile("cp.async.wait_group 1;" ::: "memory");
    else                 asm volatile("cp.async.wait_group 0;" ::: "memory");
    __syncthreads();

    uint32_t ab = sbase + slot*STAGE_BYTES;
    uint32_t bb = ab + A_ST;
    int nslot = (kt+3) & 3;
    bool pref = (kt+3 < NKC);

    #pragma unroll
    for (int ks=0; ks<4; ks++){
      uint32_t a[4][4], b[8][2];
      #pragma unroll
      for (int mf=0; mf<4; mf++){
        int row = wm*64 + mf*16 + arow_lo;
        int ko  = ks*2 + ako_hi;
        uint32_t addr = ab + (uint32_t)(row*128 + ((ko ^ (row&7))<<4));
        asm volatile("ldmatrix.sync.aligned.m8n8.x4.shared.b16 {%0,%1,%2,%3}, [%4];"
          : "=r"(a[mf][0]),"=r"(a[mf][1]),"=r"(a[mf][2]),"=r"(a[mf][3]) : "r"(addr));
      }
      #pragma unroll
      for (int p=0; p<4; p++){
        int kr = ks*16 + arow_lo;
        int no = wn*8 + p*2 + ako_hi;
        uint32_t addr = bb + (uint32_t)(kr*512 + ((no ^ (kr&7))<<4));
        asm volatile("ldmatrix.sync.aligned.m8n8.x4.trans.shared.b16 {%0,%1,%2,%3}, [%4];"
          : "=r"(b[2*p][0]),"=r"(b[2*p][1]),"=r"(b[2*p+1][0]),"=r"(b[2*p+1][1]) : "r"(addr));
      }
      #pragma unroll
      for (int mf=0; mf<4; mf++)
        #pragma unroll
        for (int nf=0; nf<8; nf++)
          asm volatile("mma.sync.aligned.m16n8k16.row.col.f32.f16.f16.f32 "
            "{%0,%1,%2,%3}, {%4,%5,%6,%7}, {%8,%9}, {%0,%1,%2,%3};"
            : "+f"(c[mf][nf][0]), "+f"(c[mf][nf][1]), "+f"(c[mf][nf][2]), "+f"(c[mf][nf][3])
            : "r"(a[mf][0]),"r"(a[mf][1]),"r"(a[mf][2]),"r"(a[mf][3]),
              "r"(b[nf][0]),"r"(b[nf][1]));

      // interleaved prefetch issue: keep LSU off the chunk-start critical path
      if (ks==0 && pref) load_A<MODE>(kt+3, nslot, tid, sbase, Xg, stok);
      if (ks==1 && pref) load_B<0>(kt+3, nslot, tid, sbase, Wb);
      if (ks==2 && pref) load_B<1>(kt+3, nslot, tid, sbase, Wb);
      if (ks==3 && pref) asm volatile("cp.async.commit_group;" ::: "memory");
    }
  }

  // ---------------- epilogue (registers -> gmem) ----------------
  int lr = lane>>2, lc = lane&3;
  const float* brow = bias + e*EDIM + n0 + wn*64;
  if (MODE==1){
    __half* hb = g_h16 + ((size_t)e*ROWS_MAX + row0)*EDIM + n0 + wn*64;
    #pragma unroll
    for (int nf=0; nf<8; nf++){
      int col = nf*8 + lc*2;
      float bv0 = brow[col], bv1 = brow[col+1];
      #pragma unroll
      for (int mf=0; mf<4; mf++){
        int r_ = wm*64 + mf*16 + lr;
        if (r_ < rows){
          __half2 h = __floats2half2_rn(fmaxf(c[mf][nf][0]+bv0,0.f), fmaxf(c[mf][nf][1]+bv1,0.f));
          *reinterpret_cast<__half2*>(hb + (size_t)r_*EDIM + col) = h;
        }
        if (r_+8 < rows){
          __half2 h = __floats2half2_rn(fmaxf(c[mf][nf][2]+bv0,0.f), fmaxf(c[mf][nf][3]+bv1,0.f));
          *reinterpret_cast<__half2*>(hb + (size_t)(r_+8)*EDIM + col) = h;
        }
      }
    }
  } else {
    float* yb = g_ybuf + ((size_t)e*ROWS_MAX + row0)*EDIM + n0 + wn*64;
    #pragma unroll
    for (int nf=0; nf<8; nf++){
      int col = nf*8 + lc*2;
      float bv0 = brow[col], bv1 = brow[col+1];
      #pragma unroll
      for (int mf=0; mf<4; mf++){
        int r_ = wm*64 + mf*16 + lr;
        if (r_ < rows)
          *reinterpret_cast<float2*>(yb + (size_t)r_*EDIM + col)
              = make_float2(c[mf][nf][0]+bv0, c[mf][nf][1]+bv1);
        if (r_+8 < rows)
          *reinterpret_cast<float2*>(yb + (size_t)(r_+8)*EDIM + col)
              = make_float2(c[mf][nf][2]+bv0, c[mf][nf][3]+bv1);
      }
    }
  }
}

// ---------------- combine: out = x + w0*y0 + w1*y1 ----------------
__global__ void combine_kernel(const float* __restrict__ x, float* __restrict__ out){
  int t = blockIdx.x;
  int c1 = g_code[2*t], c2 = g_code[2*t+1];
  int s1 = c1 & (NTOK-1), s2 = c2 & (NTOK-1);
  float w1v = (s1 < ROWS_MAX) ? g_wgt[c1] : 0.f;
  float w2v = (s2 < ROWS_MAX) ? g_wgt[c2] : 0.f;
  size_t y1o = (s1 < ROWS_MAX) ? ((size_t)(c1>>13)*ROWS_MAX + s1)*EDIM : 0;
  size_t y2o = (s2 < ROWS_MAX) ? ((size_t)(c2>>13)*ROWS_MAX + s2)*EDIM : 0;
  const float4* xr = reinterpret_cast<const float4*>(x + (size_t)t*EDIM);
  const float4* y1 = reinterpret_cast<const float4*>(g_ybuf + y1o);
  const float4* y2 = reinterpret_cast<const float4*>(g_ybuf + y2o);
  float4* o = reinterpret_cast<float4*>(out + (size_t)t*EDIM);
  for (int j = threadIdx.x; j < EDIM/4; j += blockDim.x){
    float4 a = xr[j], b = y1[j], c = y2[j];
    float4 rr;
    rr.x = a.x + w1v*b.x + w2v*c.x;
    rr.y = a.y + w1v*b.y + w2v*c.y;
    rr.z = a.z + w1v*b.z + w2v*c.z;
    rr.w = a.w + w1v*b.w + w2v*c.w;
    o[j] = rr;
  }
}

// ---------------- launch ----------------
extern "C" void kernel_launch(void* const* d_in, const int* in_sizes, int n_in,
                              void* d_out, int out_size){
  const float* x  = (const float*)d_in[0];
  const float* gw = (const float*)d_in[1];
  const float* gb = (const float*)d_in[2];
  const float* tp = (const float*)d_in[3];
  const float* w1 = (const float*)d_in[4];
  const float* b1 = (const float*)d_in[5];
  const float* w2 = (const float*)d_in[6];
  const float* b2 = (const float*)d_in[7];
  float* out = (float*)d_out;

  cudaFuncSetAttribute(moe_gemm<1>, cudaFuncAttributeMaxDynamicSharedMemorySize, SMEM_TOTAL);
  cudaFuncSetAttribute(moe_gemm<2>, cudaFuncAttributeMaxDynamicSharedMemorySize, SMEM_TOTAL);

  convert_kernel<<<1024, 256>>>(w1, w2, x);           // idx 0 (also inits counters)
  router_kernel<<<NTOK/8, 256>>>(x, gw, gb, tp);      // idx 1
  capacity_kernel<<<NEXP, 256>>>();                   // idx 2
  dim3 grid(EDIM/256, NEXP*32);
  moe_gemm<1><<<grid, 256, SMEM_TOTAL>>>(b1);         // idx 3  <-- profiled
  moe_gemm<2><<<grid, 256, SMEM_TOTAL>>>(b2);         // idx 4
  aux_kernel<<<1, 32>>>(out, out_size);               // idx 5
  combine_kernel<<<NTOK, 256>>>(x, out);              // idx 6
}

// round 10
// speedup vs baseline: 1.7272x; 1.4811x over previous
#include <cuda_runtime.h>
#include <cuda_fp16.h>
#include <cstdint>

#define NTOK   8192
#define EDIM   2048
#define NEXP   8
#define CAPACITY 2560
#define ROWS_MAX 4096
#define KC     64
#define NKC    (EDIM/KC)     // 32 K-chunks

// ---------------- device scratch (no allocs allowed) ----------------
__device__ int    g_count[NEXP];
__device__ float  g_probSum[NEXP];
__device__ int    g_tok[NEXP*NTOK];
__device__ float  g_wgt[NEXP*NTOK];
__device__ int    g_pos[NEXP*NTOK];
__device__ int    g_code[NTOK*2];
__device__ unsigned char g_drop[NEXP*NTOK];
__device__ __half g_w16[(size_t)2*NEXP*EDIM*EDIM];        // 134 MB (w1|w2 fp16)
__device__ __half g_x16[(size_t)NTOK*EDIM];               // 33 MB
__device__ __half g_h16[(size_t)NEXP*ROWS_MAX*EDIM];      // 134 MB
__device__ __half g_y16[(size_t)NEXP*ROWS_MAX*EDIM];      // 134 MB (fp16 y)

// ---------------- helpers ----------------
__device__ __forceinline__ uint32_t smem_u32(const void* p){
  uint32_t a; asm("{ .reg .u64 t; cvta.to.shared.u64 t, %1; cvt.u32.u64 %0, t; }" : "=r"(a) : "l"(p));
  return a;
}
__device__ __forceinline__ void cpa16(uint32_t dst, const void* src){
  asm volatile("cp.async.cg.shared.global [%0], [%1], 16;" :: "r"(dst), "l"(src));
}

// ---------------- fp32 -> fp16 conversion of weights and x (+ counter init) ----------------
__global__ void convert_kernel(const float* __restrict__ w1, const float* __restrict__ w2,
                               const float* __restrict__ x){
  if (blockIdx.x == 0 && threadIdx.x < NEXP){
    g_count[threadIdx.x] = 0; g_probSum[threadIdx.x] = 0.f;
  }
  const size_t NW = (size_t)NEXP*EDIM*EDIM;
  const size_t NX = (size_t)NTOK*EDIM;
  size_t i = (size_t)blockIdx.x*blockDim.x + threadIdx.x;
  size_t stride = (size_t)gridDim.x*blockDim.x;
  uint2* o1 = reinterpret_cast<uint2*>(g_w16);
  uint2* o2 = reinterpret_cast<uint2*>(g_w16 + NW);
  uint2* ox = reinterpret_cast<uint2*>(g_x16);
  const float4* s1 = reinterpret_cast<const float4*>(w1);
  const float4* s2 = reinterpret_cast<const float4*>(w2);
  const float4* sx = reinterpret_cast<const float4*>(x);
  for (size_t j=i; j<NW/4; j+=stride){
    float4 v = s1[j];
    __half2 a = __floats2half2_rn(v.x,v.y), b = __floats2half2_rn(v.z,v.w);
    o1[j] = make_uint2(*(uint32_t*)&a, *(uint32_t*)&b);
    v = s2[j];
    a = __floats2half2_rn(v.x,v.y); b = __floats2half2_rn(v.z,v.w);
    o2[j] = make_uint2(*(uint32_t*)&a, *(uint32_t*)&b);
  }
  for (size_t j=i; j<NX/4; j+=stride){
    float4 v = sx[j];
    __half2 a = __floats2half2_rn(v.x,v.y), b = __floats2half2_rn(v.z,v.w);
    ox[j] = make_uint2(*(uint32_t*)&a, *(uint32_t*)&b);
  }
}

// ---------------- router: warp per token ----------------
__global__ void router_kernel(const float* __restrict__ x, const float* __restrict__ gw,
                              const float* __restrict__ gb, const float* __restrict__ temp){
  int t = (int)((blockIdx.x*blockDim.x + threadIdx.x) >> 5);
  int lane = threadIdx.x & 31;
  if (t >= NTOK) return;
  const float* xr = x + (size_t)t * EDIM;
  float acc[8] = {0,0,0,0,0,0,0,0};
  for (int d = lane; d < EDIM; d += 32){
    float xv = xr[d];
    const float4* g4 = reinterpret_cast<const float4*>(gw + (size_t)d*NEXP);
    float4 ga = g4[0], gbv = g4[1];
    acc[0] += xv*ga.x;  acc[1] += xv*ga.y;  acc[2] += xv*ga.z;  acc[3] += xv*ga.w;
    acc[4] += xv*gbv.x; acc[5] += xv*gbv.y; acc[6] += xv*gbv.z; acc[7] += xv*gbv.w;
  }
  #pragma unroll
  for (int off=16; off; off>>=1)
    #pragma unroll
    for (int e=0;e<8;e++) acc[e] += __shfl_down_sync(0xffffffffu, acc[e], off);
  if (lane==0){
    float it = 1.0f / fabsf(temp[0]);
    float p[8]; float m = -1e30f;
    #pragma unroll
    for (int e=0;e<8;e++){ p[e] = (acc[e]+gb[e])*it; m = fmaxf(m, p[e]); }
    float s = 0.f;
    #pragma unroll
    for (int e=0;e<8;e++){ p[e] = expf(p[e]-m); s += p[e]; }
    float inv = 1.f/s;
    #pragma unroll
    for (int e=0;e<8;e++){ p[e] *= inv; atomicAdd(&g_probSum[e], p[e]); }
    int e0 = 0;
    #pragma unroll
    for (int e=1;e<8;e++) if (p[e] > p[e0]) e0 = e;
    int e1 = (e0==0) ? 1 : 0;
    #pragma unroll
    for (int e=0;e<8;e++) if (e!=e0 && p[e] > p[e1]) e1 = e;
    float rs = 1.f/(p[e0]+p[e1]);
    int s0 = atomicAdd(&g_count[e0], 1);
    g_tok[e0*NTOK+s0] = t; g_wgt[e0*NTOK+s0] = p[e0]*rs; g_pos[e0*NTOK+s0] = t*2;
    g_code[t*2+0] = e0*NTOK + s0;
    int s1 = atomicAdd(&g_count[e1], 1);
    g_tok[e1*NTOK+s1] = t; g_wgt[e1*NTOK+s1] = p[e1]*rs; g_pos[e1*NTOK+s1] = t*2+1;
    g_code[t*2+1] = e1*NTOK + s1;
  }
}

// ---------------- capacity filter (exact jax semantics; ~never triggers) ----------------
__global__ void capacity_kernel(){
  int e = blockIdx.x;
  int cnt = g_count[e];
  if (cnt <= CAPACITY) return;
  for (int i = threadIdx.x; i < cnt; i += blockDim.x){
    float wi = g_wgt[e*NTOK+i]; int pi = g_pos[e*NTOK+i];
    int rank = 0;
    for (int j=0;j<cnt;j++){
      float wj = g_wgt[e*NTOK+j];
      if (wj > wi || (wj == wi && g_pos[e*NTOK+j] < pi)) rank++;
    }
    g_drop[e*NTOK+i] = (rank >= CAPACITY) ? 1 : 0;
  }
  __syncthreads();
  for (int i = threadIdx.x; i < cnt; i += blockDim.x)
    if (g_drop[e*NTOK+i]) g_wgt[e*NTOK+i] = 0.f;
}

// ---------------- aux loss ----------------
__global__ void aux_kernel(float* __restrict__ out, int out_size){
  if (threadIdx.x != 0) return;
  float sum = 0.f;
  for (int e=0;e<NEXP;e++) sum += g_probSum[e];
  float mean = sum / NEXP;
  float var = 0.f;
  for (int e=0;e<NEXP;e++){ float d = g_probSum[e]-mean; var += d*d; }
  var /= (NEXP-1);
  float cv = sqrtf(var) / (mean + 1e-10f);
  float bal = 0.f;
  for (int e=0;e<NEXP;e++)
    bal += (g_probSum[e]/(float)NTOK) * ((float)g_count[e]/(float)NTOK);
  bal *= (float)NEXP;
  if (out_size > NTOK*EDIM) out[(size_t)NTOK*EDIM] = bal + 0.01f*cv;
}

// ---------------- fp16 mma.sync GEMM, 128Mx256Nx64K chunks ----------------
// 8 warps (2x4), warp tile 64x64, 1 CTA/SM, XOR-swizzled smem (conflict-free)
#define A_ST 16384
#define B_ST 32768
#define STAGE_BYTES (A_ST + B_ST)
#define NSTAGE 4
#define META_OFF (NSTAGE*STAGE_BYTES)       // 196608
#define SMEM_TOTAL (META_OFF + 768)

template<int MODE>
__device__ __forceinline__ void load_A(
    int kt, int slot, int tid, uint32_t sbase,
    const __half* __restrict__ Xg, const int* __restrict__ stok)
{
  int k0 = kt*KC;
  uint32_t ab = sbase + slot*STAGE_BYTES;
  #pragma unroll
  for (int i=0;i<4;i++){
    int idx = tid + i*256;
    int r = idx >> 3, ko = idx & 7;
    size_t grow = (MODE==1) ? (size_t)stok[r] : (size_t)r;
    const __half* src = Xg + grow*EDIM + k0 + ko*8;
    uint32_t dst = ab + (uint32_t)(r*128 + ((ko ^ (r&7))<<4));
    cpa16(dst, src);
  }
}
template<int HALF>
__device__ __forceinline__ void load_B(
    int kt, int slot, int tid, uint32_t sbase,
    const __half* __restrict__ Wb)
{
  int k0 = kt*KC;
  uint32_t bb = sbase + slot*STAGE_BYTES + A_ST;
  #pragma unroll
  for (int i=HALF*4;i<HALF*4+4;i++){
    int idx = tid + i*256;
    int kr = idx >> 5, no = idx & 31;
    const __half* src = Wb + (size_t)(k0+kr)*EDIM + no*8;
    uint32_t dst = bb + (uint32_t)(kr*512 + ((no ^ (kr&7))<<4));
    cpa16(dst, src);
  }
}

template<int MODE>
__global__ void __launch_bounds__(256,1) moe_gemm(
    const float* __restrict__ bias)
{
  int e  = blockIdx.y >> 5;
  int rb = blockIdx.y & 31;
  int cnt = g_count[e]; if (cnt > ROWS_MAX) cnt = ROWS_MAX;
  int row0 = rb * 128;
  if (row0 >= cnt) return;
  int rows = cnt - row0; if (rows > 128) rows = 128;
  int n0 = blockIdx.x * 256;

  extern __shared__ char smem[];
  uint32_t sbase = smem_u32(smem);
  int tid = threadIdx.x, warp = tid>>5, lane = tid&31;
  int* stok = (int*)(smem + META_OFF);

  if (tid < 128){
    int tkn = 0;
    if (MODE==1 && tid < rows) tkn = g_tok[e*NTOK + row0 + tid];
    stok[tid] = tkn;
  }
  __syncthreads();

  const __half* Xg = (MODE==1) ? g_x16 : (g_h16 + ((size_t)e*ROWS_MAX + row0)*EDIM);
  const __half* Wb = g_w16 + ((size_t)((MODE-1)*NEXP + e))*EDIM*EDIM + n0;

  float c[4][8][4];
  #pragma unroll
  for (int a=0;a<4;a++)
    #pragma unroll
    for (int b=0;b<8;b++)
      #pragma unroll
      for (int q=0;q<4;q++) c[a][b][q] = 0.f;

  int wm = warp & 1, wn = warp >> 1;   // 2x4 warp grid: 64(M) x 64(N) each

  #pragma unroll
  for (int p=0;p<3;p++){
    load_A<MODE>(p, p, tid, sbase, Xg, stok);
    load_B<0>(p, p, tid, sbase, Wb);
    load_B<1>(p, p, tid, sbase, Wb);
    asm volatile("cp.async.commit_group;" ::: "memory");
  }

  int arow_lo = (lane & 15);
  int ako_hi  = (lane >> 4);
  for (int kt=0; kt<NKC; kt++){
    int slot = kt & 3;
    if      (kt+2 < NKC) asm volatile("cp.async.wait_group 2;" ::: "memory");
    else if (kt+1 < NKC) asm volatile("cp.async.wait_group 1;" ::: "memory");
    else                 asm volatile("cp.async.wait_group 0;" ::: "memory");
    __syncthreads();

    uint32_t ab = sbase + slot*STAGE_BYTES;
    uint32_t bb = ab + A_ST;
    int nslot = (kt+3) & 3;
    bool pref = (kt+3 < NKC);

    #pragma unroll
    for (int ks=0; ks<4; ks++){
      uint32_t a[4][4], b[8][2];
      #pragma unroll
      for (int mf=0; mf<4; mf++){
        int row = wm*64 + mf*16 + arow_lo;
        int ko  = ks*2 + ako_hi;
        uint32_t addr = ab + (uint32_t)(row*128 + ((ko ^ (row&7))<<4));
        asm volatile("ldmatrix.sync.aligned.m8n8.x4.shared.b16 {%0,%1,%2,%3}, [%4];"
          : "=r"(a[mf][0]),"=r"(a[mf][1]),"=r"(a[mf][2]),"=r"(a[mf][3]) : "r"(addr));
      }
      #pragma unroll
      for (int p=0; p<4; p++){
        int kr = ks*16 + arow_lo;
        int no = wn*8 + p*2 + ako_hi;
        uint32_t addr = bb + (uint32_t)(kr*512 + ((no ^ (kr&7))<<4));
        asm volatile("ldmatrix.sync.aligned.m8n8.x4.trans.shared.b16 {%0,%1,%2,%3}, [%4];"
          : "=r"(b[2*p][0]),"=r"(b[2*p][1]),"=r"(b[2*p+1][0]),"=r"(b[2*p+1][1]) : "r"(addr));
      }
      #pragma unroll
      for (int mf=0; mf<4; mf++)
        #pragma unroll
        for (int nf=0; nf<8; nf++)
          asm volatile("mma.sync.aligned.m16n8k16.row.col.f32.f16.f16.f32 "
            "{%0,%1,%2,%3}, {%4,%5,%6,%7}, {%8,%9}, {%0,%1,%2,%3};"
            : "+f"(c[mf][nf][0]), "+f"(c[mf][nf][1]), "+f"(c[mf][nf][2]), "+f"(c[mf][nf][3])
            : "r"(a[mf][0]),"r"(a[mf][1]),"r"(a[mf][2]),"r"(a[mf][3]),
              "r"(b[nf][0]),"r"(b[nf][1]));

      if (ks==0 && pref) load_A<MODE>(kt+3, nslot, tid, sbase, Xg, stok);
      if (ks==1 && pref) load_B<0>(kt+3, nslot, tid, sbase, Wb);
      if (ks==2 && pref) load_B<1>(kt+3, nslot, tid, sbase, Wb);
      if (ks==3 && pref) asm volatile("cp.async.commit_group;" ::: "memory");
    }
  }

  // ---------------- epilogue (registers -> gmem, fp16) ----------------
  int lr = lane>>2, lc = lane&3;
  const float* brow = bias + e*EDIM + n0 + wn*64;
  __half* ob = ((MODE==1) ? g_h16 : g_y16) + ((size_t)e*ROWS_MAX + row0)*EDIM + n0 + wn*64;
  #pragma unroll
  for (int nf=0; nf<8; nf++){
    int col = nf*8 + lc*2;
    float bv0 = brow[col], bv1 = brow[col+1];
    #pragma unroll
    for (int mf=0; mf<4; mf++){
      int r_ = wm*64 + mf*16 + lr;
      if (r_ < rows){
        float v0 = c[mf][nf][0]+bv0, v1 = c[mf][nf][1]+bv1;
        if (MODE==1){ v0 = fmaxf(v0,0.f); v1 = fmaxf(v1,0.f); }
        *reinterpret_cast<__half2*>(ob + (size_t)r_*EDIM + col) = __floats2half2_rn(v0, v1);
      }
      if (r_+8 < rows){
        float v0 = c[mf][nf][2]+bv0, v1 = c[mf][nf][3]+bv1;
        if (MODE==1){ v0 = fmaxf(v0,0.f); v1 = fmaxf(v1,0.f); }
        *reinterpret_cast<__half2*>(ob + (size_t)(r_+8)*EDIM + col) = __floats2half2_rn(v0, v1);
      }
    }
  }
}

// ---------------- combine: out = x + w0*y0 + w1*y1 (y in fp16) ----------------
__global__ void combine_kernel(const float* __restrict__ x, float* __restrict__ out){
  int t = blockIdx.x;
  int c1 = g_code[2*t], c2 = g_code[2*t+1];
  int s1 = c1 & (NTOK-1), s2 = c2 & (NTOK-1);
  float w1v = (s1 < ROWS_MAX) ? g_wgt[c1] : 0.f;
  float w2v = (s2 < ROWS_MAX) ? g_wgt[c2] : 0.f;
  size_t y1o = (s1 < ROWS_MAX) ? ((size_t)(c1>>13)*ROWS_MAX + s1)*EDIM : 0;
  size_t y2o = (s2 < ROWS_MAX) ? ((size_t)(c2>>13)*ROWS_MAX + s2)*EDIM : 0;
  const float4* xr = reinterpret_cast<const float4*>(x + (size_t)t*EDIM);
  const uint2* y1 = reinterpret_cast<const uint2*>(g_y16 + y1o);
  const uint2* y2 = reinterpret_cast<const uint2*>(g_y16 + y2o);
  float4* o = reinterpret_cast<float4*>(out + (size_t)t*EDIM);
  for (int j = threadIdx.x; j < EDIM/4; j += blockDim.x){
    float4 a = xr[j];
    uint2 u1 = y1[j], u2 = y2[j];
    float2 b0 = __half22float2(*reinterpret_cast<__half2*>(&u1.x));
    float2 b1 = __half22float2(*reinterpret_cast<__half2*>(&u1.y));
    float2 c0 = __half22float2(*reinterpret_cast<__half2*>(&u2.x));
    float2 c1f = __half22float2(*reinterpret_cast<__half2*>(&u2.y));
    float4 rr;
    rr.x = a.x + w1v*b0.x + w2v*c0.x;
    rr.y = a.y + w1v*b0.y + w2v*c0.y;
    rr.z = a.z + w1v*b1.x + w2v*c1f.x;
    rr.w = a.w + w1v*b1.y + w2v*c1f.y;
    o[j] = rr;
  }
}

// ---------------- launch ----------------
extern "C" void kernel_launch(void* const* d_in, const int* in_sizes, int n_in,
                              void* d_out, int out_size){
  const float* x  = (const float*)d_in[0];
  const float* gw = (const float*)d_in[1];
  const float* gb = (const float*)d_in[2];
  const float* tp = (const float*)d_in[3];
  const float* w1 = (const float*)d_in[4];
  const float* b1 = (const float*)d_in[5];
  const float* w2 = (const float*)d_in[6];
  const float* b2 = (const float*)d_in[7];
  float* out = (float*)d_out;

  cudaFuncSetAttribute(moe_gemm<1>, cudaFuncAttributeMaxDynamicSharedMemorySize, SMEM_TOTAL);
  cudaFuncSetAttribute(moe_gemm<2>, cudaFuncAttributeMaxDynamicSharedMemorySize, SMEM_TOTAL);

  convert_kernel<<<4096, 256>>>(w1, w2, x);           // idx 0 (also inits counters)
  router_kernel<<<NTOK/8, 256>>>(x, gw, gb, tp);      // idx 1
  capacity_kernel<<<NEXP, 256>>>();                   // idx 2
  dim3 grid(EDIM/256, NEXP*32);
  moe_gemm<1><<<grid, 256, SMEM_TOTAL>>>(b1);         // idx 3  <-- profiled
  moe_gemm<2><<<grid, 256, SMEM_TOTAL>>>(b2);         // idx 4
  aux_kernel<<<1, 32>>>(out, out_size);               // idx 5
  combine_kernel<<<NTOK, 256>>>(x, out);              // idx 6
}

// round 11
// speedup vs baseline: 1.8445x; 1.0679x over previous
#include <cuda_runtime.h>
#include <cuda_fp16.h>
#include <cstdint>

#define NTOK   8192
#define EDIM   2048
#define NEXP   8
#define CAPACITY 2560
#define ROWS_MAX 4096
#define KC     64
#define NKC    (EDIM/KC)     // 32 K-chunks

// ---------------- device scratch (no allocs allowed) ----------------
__device__ int    g_count[NEXP];
__device__ float  g_probSum[NEXP];
__device__ int    g_tok[NEXP*NTOK];
__device__ float  g_wgt[NEXP*NTOK];
__device__ int    g_pos[NEXP*NTOK];
__device__ int    g_code[NTOK*2];
__device__ unsigned char g_drop[NEXP*NTOK];
__device__ __half g_w16[(size_t)2*NEXP*EDIM*EDIM];        // 134 MB (w1|w2 fp16)
__device__ __half g_x16[(size_t)NTOK*EDIM];               // 33 MB
__device__ __half g_h16[(size_t)NEXP*ROWS_MAX*EDIM];      // 134 MB
__device__ __half g_y16[(size_t)NEXP*ROWS_MAX*EDIM];      // 134 MB (fp16 y)

// ---------------- helpers ----------------
__device__ __forceinline__ uint32_t smem_u32(const void* p){
  uint32_t a; asm("{ .reg .u64 t; cvta.to.shared.u64 t, %1; cvt.u32.u64 %0, t; }" : "=r"(a) : "l"(p));
  return a;
}
__device__ __forceinline__ void cpa16(uint32_t dst, const void* src){
  asm volatile("cp.async.cg.shared.global [%0], [%1], 16;" :: "r"(dst), "l"(src));
}

// ---------------- fp32 -> fp16 conversion of weights (+ counter init) ----------------
__global__ void convert_kernel(const float* __restrict__ w1, const float* __restrict__ w2){
  if (blockIdx.x == 0 && threadIdx.x < NEXP){
    g_count[threadIdx.x] = 0; g_probSum[threadIdx.x] = 0.f;
  }
  const size_t NW = (size_t)NEXP*EDIM*EDIM;
  size_t i = (size_t)blockIdx.x*blockDim.x + threadIdx.x;
  size_t stride = (size_t)gridDim.x*blockDim.x;
  uint2* o1 = reinterpret_cast<uint2*>(g_w16);
  uint2* o2 = reinterpret_cast<uint2*>(g_w16 + NW);
  const float4* s1 = reinterpret_cast<const float4*>(w1);
  const float4* s2 = reinterpret_cast<const float4*>(w2);
  for (size_t j=i; j<NW/4; j+=stride){
    float4 v = s1[j];
    __half2 a = __floats2half2_rn(v.x,v.y), b = __floats2half2_rn(v.z,v.w);
    o1[j] = make_uint2(*(uint32_t*)&a, *(uint32_t*)&b);
    v = s2[j];
    a = __floats2half2_rn(v.x,v.y); b = __floats2half2_rn(v.z,v.w);
    o2[j] = make_uint2(*(uint32_t*)&a, *(uint32_t*)&b);
  }
}

// ---------------- router: warp per token (also emits x16) ----------------
__global__ void router_kernel(const float* __restrict__ x, const float* __restrict__ gw,
                              const float* __restrict__ gb, const float* __restrict__ temp){
  int t = (int)((blockIdx.x*blockDim.x + threadIdx.x) >> 5);
  int lane = threadIdx.x & 31;
  if (t >= NTOK) return;
  const float* xr = x + (size_t)t * EDIM;
  __half* xo = g_x16 + (size_t)t * EDIM;
  float acc[8] = {0,0,0,0,0,0,0,0};
  for (int d = lane; d < EDIM; d += 32){
    float xv = xr[d];
    xo[d] = __float2half(xv);                 // fused fp16 conversion of x
    const float4* g4 = reinterpret_cast<const float4*>(gw + (size_t)d*NEXP);
    float4 ga = g4[0], gbv = g4[1];
    acc[0] += xv*ga.x;  acc[1] += xv*ga.y;  acc[2] += xv*ga.z;  acc[3] += xv*ga.w;
    acc[4] += xv*gbv.x; acc[5] += xv*gbv.y; acc[6] += xv*gbv.z; acc[7] += xv*gbv.w;
  }
  #pragma unroll
  for (int off=16; off; off>>=1)
    #pragma unroll
    for (int e=0;e<8;e++) acc[e] += __shfl_down_sync(0xffffffffu, acc[e], off);
  if (lane==0){
    float it = 1.0f / fabsf(temp[0]);
    float p[8]; float m = -1e30f;
    #pragma unroll
    for (int e=0;e<8;e++){ p[e] = (acc[e]+gb[e])*it; m = fmaxf(m, p[e]); }
    float s = 0.f;
    #pragma unroll
    for (int e=0;e<8;e++){ p[e] = expf(p[e]-m); s += p[e]; }
    float inv = 1.f/s;
    #pragma unroll
    for (int e=0;e<8;e++){ p[e] *= inv; atomicAdd(&g_probSum[e], p[e]); }
    int e0 = 0;
    #pragma unroll
    for (int e=1;e<8;e++) if (p[e] > p[e0]) e0 = e;
    int e1 = (e0==0) ? 1 : 0;
    #pragma unroll
    for (int e=0;e<8;e++) if (e!=e0 && p[e] > p[e1]) e1 = e;
    float rs = 1.f/(p[e0]+p[e1]);
    int s0 = atomicAdd(&g_count[e0], 1);
    g_tok[e0*NTOK+s0] = t; g_wgt[e0*NTOK+s0] = p[e0]*rs; g_pos[e0*NTOK+s0] = t*2;
    g_code[t*2+0] = e0*NTOK + s0;
    int s1 = atomicAdd(&g_count[e1], 1);
    g_tok[e1*NTOK+s1] = t; g_wgt[e1*NTOK+s1] = p[e1]*rs; g_pos[e1*NTOK+s1] = t*2+1;
    g_code[t*2+1] = e1*NTOK + s1;
  }
}

// ---------------- capacity filter + aux loss (fused) ----------------
__global__ void capacity_aux_kernel(float* __restrict__ out, int out_size){
  if (blockIdx.x == NEXP){
    if (threadIdx.x == 0){
      float sum = 0.f;
      for (int e=0;e<NEXP;e++) sum += g_probSum[e];
      float mean = sum / NEXP;
      float var = 0.f;
      for (int e=0;e<NEXP;e++){ float d = g_probSum[e]-mean; var += d*d; }
      var /= (NEXP-1);
      float cv = sqrtf(var) / (mean + 1e-10f);
      float bal = 0.f;
      for (int e=0;e<NEXP;e++)
        bal += (g_probSum[e]/(float)NTOK) * ((float)g_count[e]/(float)NTOK);
      bal *= (float)NEXP;
      if (out_size > NTOK*EDIM) out[(size_t)NTOK*EDIM] = bal + 0.01f*cv;
    }
    return;
  }
  int e = blockIdx.x;
  int cnt = g_count[e];
  if (cnt <= CAPACITY) return;
  for (int i = threadIdx.x; i < cnt; i += blockDim.x){
    float wi = g_wgt[e*NTOK+i]; int pi = g_pos[e*NTOK+i];
    int rank = 0;
    for (int j=0;j<cnt;j++){
      float wj = g_wgt[e*NTOK+j];
      if (wj > wi || (wj == wi && g_pos[e*NTOK+j] < pi)) rank++;
    }
    g_drop[e*NTOK+i] = (rank >= CAPACITY) ? 1 : 0;
  }
  __syncthreads();
  for (int i = threadIdx.x; i < cnt; i += blockDim.x)
    if (g_drop[e*NTOK+i]) g_wgt[e*NTOK+i] = 0.f;
}

// ---------------- fp16 mma.sync GEMM, 128Mx256Nx64K chunks ----------------
// 8 warps (2x4), warp tile 64x64, 1 CTA/SM, XOR-swizzled smem (conflict-free)
#define A_ST 16384
#define B_ST 32768
#define STAGE_BYTES (A_ST + B_ST)
#define NSTAGE 4
#define META_OFF (NSTAGE*STAGE_BYTES)       // 196608
#define SMEM_TOTAL (META_OFF + 768)

template<int MODE>
__device__ __forceinline__ void load_A(
    int kt, int slot, int tid, uint32_t sbase,
    const __half* __restrict__ Xg, const int* __restrict__ stok)
{
  int k0 = kt*KC;
  uint32_t ab = sbase + slot*STAGE_BYTES;
  #pragma unroll
  for (int i=0;i<4;i++){
    int idx = tid + i*256;
    int r = idx >> 3, ko = idx & 7;
    size_t grow = (MODE==1) ? (size_t)stok[r] : (size_t)r;
    const __half* src = Xg + grow*EDIM + k0 + ko*8;
    uint32_t dst = ab + (uint32_t)(r*128 + ((ko ^ (r&7))<<4));
    cpa16(dst, src);
  }
}
template<int HALF>
__device__ __forceinline__ void load_B(
    int kt, int slot, int tid, uint32_t sbase,
    const __half* __restrict__ Wb)
{
  int k0 = kt*KC;
  uint32_t bb = sbase + slot*STAGE_BYTES + A_ST;
  #pragma unroll
  for (int i=HALF*4;i<HALF*4+4;i++){
    int idx = tid + i*256;
    int kr = idx >> 5, no = idx & 31;
    const __half* src = Wb + (size_t)(k0+kr)*EDIM + no*8;
    uint32_t dst = bb + (uint32_t)(kr*512 + ((no ^ (kr&7))<<4));
    cpa16(dst, src);
  }
}

// one ks step: ldmatrix + 32 HMMA
__device__ __forceinline__ void ks_step(
    uint32_t ab, uint32_t bb, int wm, int wn, int arow_lo, int ako_hi, int ks,
    float (&c)[4][8][4])
{
  uint32_t a[4][4], b[8][2];
  #pragma unroll
  for (int mf=0; mf<4; mf++){
    int row = wm*64 + mf*16 + arow_lo;
    int ko  = ks*2 + ako_hi;
    uint32_t addr = ab + (uint32_t)(row*128 + ((ko ^ (row&7))<<4));
    asm volatile("ldmatrix.sync.aligned.m8n8.x4.shared.b16 {%0,%1,%2,%3}, [%4];"
      : "=r"(a[mf][0]),"=r"(a[mf][1]),"=r"(a[mf][2]),"=r"(a[mf][3]) : "r"(addr));
  }
  #pragma unroll
  for (int p=0; p<4; p++){
    int kr = ks*16 + arow_lo;
    int no = wn*8 + p*2 + ako_hi;
    uint32_t addr = bb + (uint32_t)(kr*512 + ((no ^ (kr&7))<<4));
    asm volatile("ldmatrix.sync.aligned.m8n8.x4.trans.shared.b16 {%0,%1,%2,%3}, [%4];"
      : "=r"(b[2*p][0]),"=r"(b[2*p][1]),"=r"(b[2*p+1][0]),"=r"(b[2*p+1][1]) : "r"(addr));
  }
  #pragma unroll
  for (int mf=0; mf<4; mf++)
    #pragma unroll
    for (int nf=0; nf<8; nf++)
      asm volatile("mma.sync.aligned.m16n8k16.row.col.f32.f16.f16.f32 "
        "{%0,%1,%2,%3}, {%4,%5,%6,%7}, {%8,%9}, {%0,%1,%2,%3};"
        : "+f"(c[mf][nf][0]), "+f"(c[mf][nf][1]), "+f"(c[mf][nf][2]), "+f"(c[mf][nf][3])
        : "r"(a[mf][0]),"r"(a[mf][1]),"r"(a[mf][2]),"r"(a[mf][3]),
          "r"(b[nf][0]),"r"(b[nf][1]));
}

template<int MODE>
__global__ void __launch_bounds__(256,1) moe_gemm(
    const float* __restrict__ bias)
{
  int e  = blockIdx.y >> 5;
  int rb = blockIdx.y & 31;
  int cnt = g_count[e]; if (cnt > ROWS_MAX) cnt = ROWS_MAX;
  int row0 = rb * 128;
  if (row0 >= cnt) return;
  int rows = cnt - row0; if (rows > 128) rows = 128;
  int n0 = blockIdx.x * 256;

  extern __shared__ char smem[];
  uint32_t sbase = smem_u32(smem);
  int tid = threadIdx.x, warp = tid>>5, lane = tid&31;
  int* stok = (int*)(smem + META_OFF);

  if (tid < 128){
    int tkn = 0;
    if (MODE==1 && tid < rows) tkn = g_tok[e*NTOK + row0 + tid];
    stok[tid] = tkn;
  }
  __syncthreads();

  const __half* Xg = (MODE==1) ? g_x16 : (g_h16 + ((size_t)e*ROWS_MAX + row0)*EDIM);
  const __half* Wb = g_w16 + ((size_t)((MODE-1)*NEXP + e))*EDIM*EDIM + n0;

  float c[4][8][4];
  #pragma unroll
  for (int a=0;a<4;a++)
    #pragma unroll
    for (int b=0;b<8;b++)
      #pragma unroll
      for (int q=0;q<4;q++) c[a][b][q] = 0.f;

  int wm = warp & 1, wn = warp >> 1;   // 2x4 warp grid: 64(M) x 64(N) each

  #pragma unroll
  for (int p=0;p<3;p++){
    load_A<MODE>(p, p, tid, sbase, Xg, stok);
    load_B<0>(p, p, tid, sbase, Wb);
    load_B<1>(p, p, tid, sbase, Wb);
    asm volatile("cp.async.commit_group;" ::: "memory");
  }

  int arow_lo = (lane & 15);
  int ako_hi  = (lane >> 4);

  // steady state: prefetch kt+3 each chunk
  #pragma unroll 4
  for (int kt=0; kt<NKC-3; kt++){
    int slot = kt & 3;
    asm volatile("cp.async.wait_group 2;" ::: "memory");
    __syncthreads();
    uint32_t ab = sbase + slot*STAGE_BYTES;
    uint32_t bb = ab + A_ST;
    int nslot = (kt+3) & 3;
    ks_step(ab, bb, wm, wn, arow_lo, ako_hi, 0, c);
    load_A<MODE>(kt+3, nslot, tid, sbase, Xg, stok);
    ks_step(ab, bb, wm, wn, arow_lo, ako_hi, 1, c);
    load_B<0>(kt+3, nslot, tid, sbase, Wb);
    ks_step(ab, bb, wm, wn, arow_lo, ako_hi, 2, c);
    load_B<1>(kt+3, nslot, tid, sbase, Wb);
    ks_step(ab, bb, wm, wn, arow_lo, ako_hi, 3, c);
    asm volatile("cp.async.commit_group;" ::: "memory");
  }
  // tail: 3 chunks, no prefetch
  #pragma unroll
  for (int kt=NKC-3; kt<NKC; kt++){
    int slot = kt & 3;
    if      (kt == NKC-3) asm volatile("cp.async.wait_group 2;" ::: "memory");
    else if (kt == NKC-2) asm volatile("cp.async.wait_group 1;" ::: "memory");
    else                  asm volatile("cp.async.wait_group 0;" ::: "memory");
    __syncthreads();
    uint32_t ab = sbase + slot*STAGE_BYTES;
    uint32_t bb = ab + A_ST;
    #pragma unroll
    for (int ks=0; ks<4; ks++) ks_step(ab, bb, wm, wn, arow_lo, ako_hi, ks, c);
  }

  // ---------------- epilogue (registers -> gmem, fp16) ----------------
  int lr = lane>>2, lc = lane&3;
  const float* brow = bias + e*EDIM + n0 + wn*64;
  __half* ob = ((MODE==1) ? g_h16 : g_y16) + ((size_t)e*ROWS_MAX + row0)*EDIM + n0 + wn*64;
  #pragma unroll
  for (int nf=0; nf<8; nf++){
    int col = nf*8 + lc*2;
    float bv0 = brow[col], bv1 = brow[col+1];
    #pragma unroll
    for (int mf=0; mf<4; mf++){
      int r_ = wm*64 + mf*16 + lr;
      if (r_ < rows){
        float v0 = c[mf][nf][0]+bv0, v1 = c[mf][nf][1]+bv1;
        if (MODE==1){ v0 = fmaxf(v0,0.f); v1 = fmaxf(v1,0.f); }
        *reinterpret_cast<__half2*>(ob + (size_t)r_*EDIM + col) = __floats2half2_rn(v0, v1);
      }
      if (r_+8 < rows){
        float v0 = c[mf][nf][2]+bv0, v1 = c[mf][nf][3]+bv1;
        if (MODE==1){ v0 = fmaxf(v0,0.f); v1 = fmaxf(v1,0.f); }
        *reinterpret_cast<__half2*>(ob + (size_t)(r_+8)*EDIM + col) = __floats2half2_rn(v0, v1);
      }
    }
  }
}

// ---------------- combine: out = x + w0*y0 + w1*y1 (y in fp16) ----------------
__global__ void combine_kernel(const float* __restrict__ x, float* __restrict__ out){
  int t = blockIdx.x;
  int c1 = g_code[2*t], c2 = g_code[2*t+1];
  int s1 = c1 & (NTOK-1), s2 = c2 & (NTOK-1);
  float w1v = (s1 < ROWS_MAX) ? g_wgt[c1] : 0.f;
  float w2v = (s2 < ROWS_MAX) ? g_wgt[c2] : 0.f;
  size_t y1o = (s1 < ROWS_MAX) ? ((size_t)(c1>>13)*ROWS_MAX + s1)*EDIM : 0;
  size_t y2o = (s2 < ROWS_MAX) ? ((size_t)(c2>>13)*ROWS_MAX + s2)*EDIM : 0;
  const float4* xr = reinterpret_cast<const float4*>(x + (size_t)t*EDIM);
  const uint2* y1 = reinterpret_cast<const uint2*>(g_y16 + y1o);
  const uint2* y2 = reinterpret_cast<const uint2*>(g_y16 + y2o);
  float4* o = reinterpret_cast<float4*>(out + (size_t)t*EDIM);
  for (int j = threadIdx.x; j < EDIM/4; j += blockDim.x){
    float4 a = xr[j];
    uint2 u1 = y1[j], u2 = y2[j];
    float2 b0 = __half22float2(*reinterpret_cast<__half2*>(&u1.x));
    float2 b1 = __half22float2(*reinterpret_cast<__half2*>(&u1.y));
    float2 c0 = __half22float2(*reinterpret_cast<__half2*>(&u2.x));
    float2 c1f = __half22float2(*reinterpret_cast<__half2*>(&u2.y));
    float4 rr;
    rr.x = a.x + w1v*b0.x + w2v*c0.x;
    rr.y = a.y + w1v*b0.y + w2v*c0.y;
    rr.z = a.z + w1v*b1.x + w2v*c1f.x;
    rr.w = a.w + w1v*b1.y + w2v*c1f.y;
    o[j] = rr;
  }
}

// ---------------- launch ----------------
extern "C" void kernel_launch(void* const* d_in, const int* in_sizes, int n_in,
                              void* d_out, int out_size){
  const float* x  = (const float*)d_in[0];
  const float* gw = (const float*)d_in[1];
  const float* gb = (const float*)d_in[2];
  const float* tp = (const float*)d_in[3];
  const float* w1 = (const float*)d_in[4];
  const float* b1 = (const float*)d_in[5];
  const float* w2 = (const float*)d_in[6];
  const float* b2 = (const float*)d_in[7];
  float* out = (float*)d_out;

  cudaFuncSetAttribute(moe_gemm<1>, cudaFuncAttributeMaxDynamicSharedMemorySize, SMEM_TOTAL);
  cudaFuncSetAttribute(moe_gemm<2>, cudaFuncAttributeMaxDynamicSharedMemorySize, SMEM_TOTAL);

  convert_kernel<<<4096, 256>>>(w1, w2);              // idx 0 (weights only + init)
  router_kernel<<<NTOK/8, 256>>>(x, gw, gb, tp);      // idx 1 (also emits x16)
  capacity_aux_kernel<<<NEXP+1, 256>>>(out, out_size);// idx 2
  dim3 grid(EDIM/256, NEXP*32);
  moe_gemm<1><<<grid, 256, SMEM_TOTAL>>>(b1);         // idx 3  <-- profiled
  moe_gemm<2><<<grid, 256, SMEM_TOTAL>>>(b2);         // idx 4
  combine_kernel<<<NTOK, 256>>>(x, out);              // idx 5
}